// round 9
// baseline (speedup 1.0000x reference)
#include <cuda_runtime.h>
#include <cuda.h>
#include <cstdint>

// involution: out[b, g*64+c, h, w] = sum_{kh,kw} x[b, g*64+c, h+kh-3, w+kw-3] * wt[b,g,kh,kw,h,w]
// B=8, G=8, CPG=64, H=W=64, K=7, pad=3, stride=1.
// 2x2 register blocking + TMA x-tile loads (box 64x14x2, dense rows, OOB zero-fill in h),
// w-halo handled by predicated edge loads. 4 pair-buffer mbarrier ring, distance-3 prefetch.

#define NTHREADS 128
#define TH 8
#define ROWS 14
#define RW 64                          // dense row width (floats)
#define PLANE_FLOATS (ROWS * RW)       // 896
#define PAIR_BYTES (2 * PLANE_FLOATS * 4)  // 7168 = 56*128
#define NPAIR 4
#define DATA_OFF 128

__device__ __forceinline__ unsigned long long pk2(float lo, float hi) {
    unsigned long long r;
    asm("mov.b64 %0, {%1, %2};" : "=l"(r) : "f"(lo), "f"(hi));
    return r;
}
__device__ __forceinline__ unsigned long long ffma2(unsigned long long a,
                                                    unsigned long long b,
                                                    unsigned long long c) {
    unsigned long long d;
    asm("fma.rn.f32x2 %0, %1, %2, %3;" : "=l"(d) : "l"(a), "l"(b), "l"(c));
    return d;
}
__device__ __forceinline__ float f2lo(unsigned long long v) {
    float a, b;
    asm("mov.b64 {%0, %1}, %2;" : "=f"(a), "=f"(b) : "l"(v));
    return a;
}
__device__ __forceinline__ float f2hi(unsigned long long v) {
    float a, b;
    asm("mov.b64 {%0, %1}, %2;" : "=f"(a), "=f"(b) : "l"(v));
    return b;
}

#define MBAR_INIT(addr, cnt) \
    asm volatile("mbarrier.init.shared.b64 [%0], %1;" :: "r"(addr), "r"(cnt) : "memory")
#define MBAR_EXPECT_TX(addr, bytes) \
    asm volatile("mbarrier.arrive.expect_tx.shared.b64 _, [%0], %1;" :: "r"(addr), "r"(bytes) : "memory")
#define TMA_LOAD3(dst, tmapp, cx, cy, cz, bar) \
    asm volatile("cp.async.bulk.tensor.3d.shared::cta.global.tile.mbarrier::complete_tx::bytes " \
                 "[%0], [%1, {%2, %3, %4}], [%5];" \
                 :: "r"(dst), "l"(tmapp), "r"(cx), "r"(cy), "r"(cz), "r"(bar) : "memory")

__device__ __forceinline__ void mbar_wait(unsigned addr, unsigned parity) {
    asm volatile(
        "{\n\t"
        ".reg .pred P;\n\t"
        "WL_%=:\n\t"
        "mbarrier.try_wait.parity.acquire.cta.shared::cta.b64 P, [%0], %1, 0x989680;\n\t"
        "@P bra.uni WD_%=;\n\t"
        "bra.uni WL_%=;\n\t"
        "WD_%=:\n\t"
        "}" :: "r"(addr), "r"(parity) : "memory");
}

__global__ void __launch_bounds__(NTHREADS, 2) involution_kernel(
    const __grid_constant__ CUtensorMap tmap,
    const float* __restrict__ wt, float* __restrict__ out)
{
    __shared__ __align__(128) char smem[DATA_OFF + NPAIR * PAIR_BYTES];
    float* bufs = (float*)(smem + DATA_OFF);

    const int tid = threadIdx.x;
    const int bid = blockIdx.x;
    const int ht = bid & 7;
    const int g  = (bid >> 3) & 7;
    const int b  = bid >> 6;
    const int h0 = ht * TH;
    const int wp = tid & 31;
    const int hq = tid >> 5;        // 0..3
    const int ha = h0 + 2 * hq;
    const int wa = 2 * wp;

    const bool okQ1 = (wp >= 1);    // cols wa-2,wa-1
    const bool okQ3 = (wp <= 30);   // cols wa+2,wa+3
    const bool okS0 = (wp >= 2);    // col wa-3
    const bool okS6 = (wp <= 29);   // col wa+4

    unsigned sbase;
    {
        unsigned long long t;
        asm("cvta.to.shared.u64 %0, %1;" : "=l"(t) : "l"((const void*)smem));
        sbase = (unsigned)t;
    }
    const unsigned dbase = sbase + DATA_OFF;
    const int plane0 = (b * 8 + g) * 64;

    if (tid == 0) {
#pragma unroll
        for (int i = 0; i < NPAIR; i++) MBAR_INIT(sbase + i * 8, 1);
        asm volatile("fence.proxy.async.shared::cta;" ::: "memory");
    }
    __syncthreads();
    if (tid == 0) {
#pragma unroll
        for (int pre = 0; pre < 3; pre++) {
            MBAR_EXPECT_TX(sbase + pre * 8, (unsigned)PAIR_BYTES);
            TMA_LOAD3(dbase + pre * PAIR_BYTES, &tmap, 0, h0 - 3,
                      plane0 + 2 * pre, sbase + pre * 8);
        }
    }

    // ---- weights: rows ha and hb=ha+1.
    // even out (col wa):   s0*t0 + Q1*(t1,t2) + Q2*(t3,t4) + Q3*(t5,t6)
    // odd  out (col wa+1): Q1*(t0,t1) + Q2*(t2,t3) + Q3*(t4,t5) + s6*t6
    const float* wbase = wt + ((b * 8 + g) * 49) * 4096 + ha * 64 + wa;
    unsigned long long WEa[7][3], WOa[7][3], WEb[7][3], WOb[7][3];
    float WEsa[7], WOsa[7], WEsb[7], WOsb[7];
#pragma unroll
    for (int kh = 0; kh < 7; kh++) {
        float wea[7], woa[7], web[7], wob[7];
#pragma unroll
        for (int kw = 0; kw < 7; kw++) {
            const float* wp2 = wbase + (kh * 7 + kw) * 4096;
            float2 pa = *(const float2*)wp2;
            float2 pb = *(const float2*)(wp2 + 64);
            wea[kw] = pa.x; woa[kw] = pa.y;
            web[kw] = pb.x; wob[kw] = pb.y;
        }
        WEa[kh][0] = pk2(wea[1], wea[2]); WEa[kh][1] = pk2(wea[3], wea[4]); WEa[kh][2] = pk2(wea[5], wea[6]);
        WEsa[kh] = wea[0];
        WOa[kh][0] = pk2(woa[0], woa[1]); WOa[kh][1] = pk2(woa[2], woa[3]); WOa[kh][2] = pk2(woa[4], woa[5]);
        WOsa[kh] = woa[6];
        WEb[kh][0] = pk2(web[1], web[2]); WEb[kh][1] = pk2(web[3], web[4]); WEb[kh][2] = pk2(web[5], web[6]);
        WEsb[kh] = web[0];
        WOb[kh][0] = pk2(wob[0], wob[1]); WOb[kh][1] = pk2(wob[2], wob[3]); WOb[kh][2] = pk2(wob[4], wob[5]);
        WOsb[kh] = wob[6];
    }

    float* oga = out + (plane0 * 4096) + ha * 64 + wa;

#pragma unroll 1
    for (int p = 0; p < 32; p++) {
        __syncthreads();   // all threads done with pair p-1 -> its buffer (== p+3's) reusable
        if (tid == 0 && p < 29) {
            const int pp = p + 3;
            MBAR_EXPECT_TX(sbase + (pp & 3) * 8, (unsigned)PAIR_BYTES);
            TMA_LOAD3(dbase + (pp & 3) * PAIR_BYTES, &tmap, 0, h0 - 3,
                      plane0 + 2 * pp, sbase + (pp & 3) * 8);
        }
        mbar_wait(sbase + (p & 3) * 8, (unsigned)((p >> 2) & 1));

        const float* sb0 = bufs + (p & 3) * (2 * PLANE_FLOATS) + (2 * hq) * RW + wa;
#pragma unroll
        for (int q = 0; q < 2; q++) {
            const float* sb = sb0 + q * PLANE_FLOATS;
            unsigned long long aeA = 0, aoA = 0, aeB = 0, aoB = 0;
            float seA = 0.f, soA = 0.f, seB = 0.f, soB = 0.f;
#pragma unroll
            for (int r = 0; r < 8; r++) {
                const float* rowp = sb + r * RW;
                unsigned long long Q1 = okQ1 ? *(const unsigned long long*)(rowp - 2) : 0ULL;
                unsigned long long Q2 = *(const unsigned long long*)(rowp);
                unsigned long long Q3 = okQ3 ? *(const unsigned long long*)(rowp + 2) : 0ULL;
                float S0 = okS0 ? rowp[-3] : 0.0f;
                float S6 = okS6 ? rowp[4]  : 0.0f;
                if (r < 7) {
                    aeA = ffma2(Q1, WEa[r][0], aeA);
                    aoA = ffma2(Q1, WOa[r][0], aoA);
                    aeA = ffma2(Q2, WEa[r][1], aeA);
                    aoA = ffma2(Q2, WOa[r][1], aoA);
                    aeA = ffma2(Q3, WEa[r][2], aeA);
                    aoA = ffma2(Q3, WOa[r][2], aoA);
                    seA = fmaf(S0, WEsa[r], seA);
                    soA = fmaf(S6, WOsa[r], soA);
                }
                if (r > 0) {
                    aeB = ffma2(Q1, WEb[r - 1][0], aeB);
                    aoB = ffma2(Q1, WOb[r - 1][0], aoB);
                    aeB = ffma2(Q2, WEb[r - 1][1], aeB);
                    aoB = ffma2(Q2, WOb[r - 1][1], aoB);
                    aeB = ffma2(Q3, WEb[r - 1][2], aeB);
                    aoB = ffma2(Q3, WOb[r - 1][2], aoB);
                    seB = fmaf(S0, WEsb[r - 1], seB);
                    soB = fmaf(S6, WOsb[r - 1], soB);
                }
            }
            float* oc = oga + (2 * p + q) * 4096;
            *(float2*)oc        = make_float2(f2lo(aeA) + f2hi(aeA) + seA, f2lo(aoA) + f2hi(aoA) + soA);
            *(float2*)(oc + 64) = make_float2(f2lo(aeB) + f2hi(aeB) + seB, f2lo(aoB) + f2hi(aoB) + soB);
        }
    }
}

typedef CUresult (*PFN_encodeTiled)(
    CUtensorMap*, CUtensorMapDataType, cuuint32_t, void*,
    const cuuint64_t*, const cuuint64_t*, const cuuint32_t*, const cuuint32_t*,
    CUtensorMapInterleave, CUtensorMapSwizzle, CUtensorMapL2promotion,
    CUtensorMapFloatOOBfill);

extern "C" void kernel_launch(void* const* d_in, const int* in_sizes, int n_in,
                              void* d_out, int out_size) {
    const float* x  = (const float*)d_in[0];
    const float* wt = (const float*)d_in[1];
    if (n_in >= 2 && in_sizes[0] == 8 * 8 * 7 * 7 * 64 * 64) {
        const float* t = x; x = wt; wt = t;
    }
    float* out = (float*)d_out;

    void* fn = nullptr;
    cudaDriverEntryPointQueryResult qr;
    cudaGetDriverEntryPointByVersion("cuTensorMapEncodeTiled", &fn, 12000,
                                     cudaEnableDefault, &qr);
    CUtensorMap tmap;
    cuuint64_t dims[3]    = {64, 64, 4096};
    cuuint64_t strides[2] = {64 * 4, 64 * 64 * 4};
    cuuint32_t box[3]     = {RW, ROWS, 2};
    cuuint32_t es[3]      = {1, 1, 1};
    CUresult rc = ((PFN_encodeTiled)fn)(&tmap, CU_TENSOR_MAP_DATA_TYPE_FLOAT32, 3, (void*)x,
                          dims, strides, box, es,
                          CU_TENSOR_MAP_INTERLEAVE_NONE, CU_TENSOR_MAP_SWIZZLE_NONE,
                          CU_TENSOR_MAP_L2_PROMOTION_L2_128B,
                          CU_TENSOR_MAP_FLOAT_OOB_FILL_NONE);
    if (rc != CUDA_SUCCESS) return;   // fail loudly (output stays poisoned) rather than trap

    involution_kernel<<<512, NTHREADS>>>(tmap, wt, out);
}

// round 10
// speedup vs baseline: 3.4617x; 3.4617x over previous
#include <cuda_runtime.h>

// involution: out[b, g*64+c, h, w] = sum_{kh,kw} x[b, g*64+c, h+kh-3, w+kw-3] * wt[b,g,kh,kw,h,w]
// B=8, G=8, CPG=64, H=W=64, K=7, pad=3, stride=1.
// 2x2 register blocking; smem word = global col + 4 (words 1..3 / 68..70 are permanent-zero halo);
// cp.async.16 interior loads; scalar edge taps via warp shuffle; 8-buffer pipeline, 2 ch/barrier.

#define NTHREADS 128
#define TH 8
#define ROWS 14
#define SMW 80
#define PLANE (ROWS * SMW)     // 1120 floats / channel
#define NBUF 8

__device__ __forceinline__ unsigned long long pk2(float lo, float hi) {
    unsigned long long r;
    asm("mov.b64 %0, {%1, %2};" : "=l"(r) : "f"(lo), "f"(hi));
    return r;
}
__device__ __forceinline__ unsigned long long ffma2(unsigned long long a,
                                                    unsigned long long b,
                                                    unsigned long long c) {
    unsigned long long d;
    asm("fma.rn.f32x2 %0, %1, %2, %3;" : "=l"(d) : "l"(a), "l"(b), "l"(c));
    return d;
}
__device__ __forceinline__ float f2lo(unsigned long long v) {
    float a, b;
    asm("mov.b64 {%0, %1}, %2;" : "=f"(a), "=f"(b) : "l"(v));
    return a;
}
__device__ __forceinline__ float f2hi(unsigned long long v) {
    float a, b;
    asm("mov.b64 {%0, %1}, %2;" : "=f"(a), "=f"(b) : "l"(v));
    return b;
}
__device__ __forceinline__ void cp_async16(unsigned dst, const void* src) {
    asm volatile("cp.async.cg.shared.global [%0], [%1], 16;" :: "r"(dst), "l"(src));
}
__device__ __forceinline__ void cp_commit() {
    asm volatile("cp.async.commit_group;");
}
__device__ __forceinline__ void cp_wait4() {
    asm volatile("cp.async.wait_group 4;");
}

__global__ void __launch_bounds__(NTHREADS, 2) involution_kernel(
    const float* __restrict__ x, const float* __restrict__ wt, float* __restrict__ out)
{
    __shared__ __align__(16) float sbuf[NBUF * PLANE];   // 35840 B

    const int tid = threadIdx.x;
    const int bid = blockIdx.x;
    const int ht = bid & 7;
    const int g  = (bid >> 3) & 7;
    const int b  = bid >> 6;
    const int h0 = ht * TH;
    const int wp = tid & 31;
    const int hq = tid >> 5;         // 0..3
    const int ha = h0 + 2 * hq;
    const int wa = 2 * wp;

    unsigned sbase;
    {
        unsigned long long t;
        asm("cvta.to.shared.u64 %0, %1;" : "=l"(t) : "l"((const void*)sbuf));
        sbase = (unsigned)t;
    }

    // zero everything once: halo words + OOB rows stay zero forever
    for (int i = tid; i < NBUF * PLANE; i += NTHREADS) sbuf[i] = 0.0f;

    // ---- weights, rows ha (set A) and ha+1 (set B).
    // even out: S0*t0 + Q1*(t1,t2) + Q2*(t3,t4) + Q3*(t5,t6)
    // odd  out: Q1*(u0,u1) + Q2*(u2,u3) + Q3*(u4,u5) + S6*u6
    // scalar pair per kh: WS = (t0 [0 if wp<2], u6 [0 if wp>29]) multiplied by SV=(S0,S6).
    const float* wbase = wt + ((b * 8 + g) * 49) * 4096 + ha * 64 + wa;
    unsigned long long WEa[7][3], WOa[7][3], WSa[7], WEb[7][3], WOb[7][3], WSb[7];
    const bool okL = (wp >= 2), okR = (wp <= 29);
#pragma unroll
    for (int kh = 0; kh < 7; kh++) {
        float wea[7], woa[7], web[7], wob[7];
#pragma unroll
        for (int kw = 0; kw < 7; kw++) {
            const float* wp2 = wbase + (kh * 7 + kw) * 4096;
            float2 pa = *(const float2*)wp2;
            float2 pb = *(const float2*)(wp2 + 64);
            wea[kw] = pa.x; woa[kw] = pa.y;
            web[kw] = pb.x; wob[kw] = pb.y;
        }
        WEa[kh][0] = pk2(wea[1], wea[2]); WEa[kh][1] = pk2(wea[3], wea[4]); WEa[kh][2] = pk2(wea[5], wea[6]);
        WOa[kh][0] = pk2(woa[0], woa[1]); WOa[kh][1] = pk2(woa[2], woa[3]); WOa[kh][2] = pk2(woa[4], woa[5]);
        WSa[kh]    = pk2(okL ? wea[0] : 0.f, okR ? woa[6] : 0.f);
        WEb[kh][0] = pk2(web[1], web[2]); WEb[kh][1] = pk2(web[3], web[4]); WEb[kh][2] = pk2(web[5], web[6]);
        WOb[kh][0] = pk2(wob[0], wob[1]); WOb[kh][1] = pk2(wob[2], wob[3]); WOb[kh][2] = pk2(wob[4], wob[5]);
        WSb[kh]    = pk2(okL ? web[0] : 0.f, okR ? wob[6] : 0.f);
    }

    // ---- interior cp.async.16 slots: 14 rows x 16 chunks = 224 slots, 2 per thread
    unsigned sd0, sd1;
    int go0, go1;
    bool p0, p1;
    {
        int i0 = tid, i1 = tid + NTHREADS;
        int r0 = i0 >> 4, c0 = i0 & 15;
        int r1 = i1 >> 4, c1 = i1 & 15;
        sd0 = (unsigned)((r0 * SMW + 4 + c0 * 4) * 4);
        sd1 = (unsigned)((r1 * SMW + 4 + c1 * 4) * 4);
        go0 = (h0 - 3 + r0) * 64 + c0 * 4;
        go1 = (h0 - 3 + r1) * 64 + c1 * 4;
        p0 = (h0 - 3 + r0 >= 0) && (h0 - 3 + r0 < 64);
        p1 = (i1 < 224) && (h0 - 3 + r1 >= 0) && (h0 - 3 + r1 < 64);
    }

    const float* xg = x + ((b * 8 + g) * 64) * 4096;
    float* oga = out + ((b * 8 + g) * 64) * 4096 + ha * 64 + wa;

    __syncthreads();   // zero-fill visible before any cp.async lands

    // ---- prologue: channels 0..3, one commit group each
#pragma unroll
    for (int pre = 0; pre < 4; pre++) {
        unsigned dbase = sbase + (unsigned)(pre * PLANE * 4);
        const float* xs = xg + pre * 4096;
        if (p0) cp_async16(dbase + sd0, xs + go0);
        if (p1) cp_async16(dbase + sd1, xs + go1);
        cp_commit();
    }

#pragma unroll 1
    for (int i = 0; i < 32; i++) {
        const int c0ch = 2 * i;
        // issue channels c0+4, c0+5 (commit always, even empty, to keep group math uniform)
#pragma unroll
        for (int q = 0; q < 2; q++) {
            int cl = c0ch + 4 + q;
            if (cl < 64) {
                unsigned dbase = sbase + (unsigned)(((cl & 7) * PLANE) * 4);
                const float* xs = xg + cl * 4096;
                if (p0) cp_async16(dbase + sd0, xs + go0);
                if (p1) cp_async16(dbase + sd1, xs + go1);
            }
            cp_commit();
        }
        cp_wait4();          // channels c0, c0+1 landed (this thread's groups)
        __syncthreads();     // + everyone else's; also protects buffer reuse

#pragma unroll
        for (int q = 0; q < 2; q++) {
            const int c = c0ch + q;
            const float* base = sbuf + (c & 7) * PLANE + (2 * hq) * SMW + wa;
            unsigned long long aeA = 0, aoA = 0, asA = 0, aeB = 0, aoB = 0, asB = 0;
#pragma unroll
            for (int r = 0; r < 8; r++) {
                const float* rowp = base + r * SMW;
                unsigned long long Q1 = *(const unsigned long long*)(rowp + 2);
                unsigned long long Q2 = *(const unsigned long long*)(rowp + 4);
                unsigned long long Q3 = *(const unsigned long long*)(rowp + 6);
                // scalar edge taps from neighbors' Q2
                float s0 = __shfl_up_sync(0xffffffffu, f2hi(Q2), 2);   // col wa-3 (garbage if wp<2, weight=0)
                float s6 = __shfl_down_sync(0xffffffffu, f2lo(Q2), 2); // col wa+4 (garbage if wp>29, weight=0)
                unsigned long long SV = pk2(s0, s6);
                if (r < 7) {
                    aeA = ffma2(Q1, WEa[r][0], aeA);
                    aoA = ffma2(Q1, WOa[r][0], aoA);
                    aeA = ffma2(Q2, WEa[r][1], aeA);
                    aoA = ffma2(Q2, WOa[r][1], aoA);
                    aeA = ffma2(Q3, WEa[r][2], aeA);
                    aoA = ffma2(Q3, WOa[r][2], aoA);
                    asA = ffma2(SV, WSa[r], asA);
                }
                if (r > 0) {
                    aeB = ffma2(Q1, WEb[r - 1][0], aeB);
                    aoB = ffma2(Q1, WOb[r - 1][0], aoB);
                    aeB = ffma2(Q2, WEb[r - 1][1], aeB);
                    aoB = ffma2(Q2, WOb[r - 1][1], aoB);
                    aeB = ffma2(Q3, WEb[r - 1][2], aeB);
                    aoB = ffma2(Q3, WOb[r - 1][2], aoB);
                    asB = ffma2(SV, WSb[r - 1], asB);
                }
            }
            float* oc = oga + c * 4096;
            *(float2*)oc        = make_float2(f2lo(aeA) + f2hi(aeA) + f2lo(asA),
                                              f2lo(aoA) + f2hi(aoA) + f2hi(asA));
            *(float2*)(oc + 64) = make_float2(f2lo(aeB) + f2hi(aeB) + f2lo(asB),
                                              f2lo(aoB) + f2hi(aoB) + f2hi(asB));
        }
    }
}

extern "C" void kernel_launch(void* const* d_in, const int* in_sizes, int n_in,
                              void* d_out, int out_size) {
    const float* x  = (const float*)d_in[0];
    const float* wt = (const float*)d_in[1];
    if (n_in >= 2 && in_sizes[0] == 8 * 8 * 7 * 7 * 64 * 64) {
        const float* t = x; x = wt; wt = t;
    }
    float* out = (float*)d_out;
    involution_kernel<<<512, NTHREADS>>>(x, wt, out);
}